// round 13
// baseline (speedup 1.0000x reference)
#include <cuda_runtime.h>
#include <cuda_fp16.h>

#define HH 128
#define WW 256
#define SS 12
#define CC 32
#define BAND 74
#define HW (HH * WW)
#define WP 264
#define HP 130
#define PLANE (HP * WP)
#define NBLK 256

// Band pair table, fp16 with baked scale (C = 7/32*log2(e)); 4B access only.
__device__ __half2 g_band2h[HH * BAND * WW];     // 9.7 MB
__device__ float g_noiseA[SS * PLANE];
__device__ float g_noiseB[SS * PLANE];
__device__ float2 g_mdsv[HW];

// Grid barrier state (zero-init; gen monotonic across graph replays).
__device__ unsigned g_cnt[4];
__device__ volatile unsigned g_gen[4];

#define FMA2(d, a, b, c) \
    asm("fma.rn.f32x2 %0, %1, %2, %3;" : "=l"(d) : "l"(a), "l"(b), "l"(c))
#define PACK2(out, v) \
    asm("mov.b64 %0, {%1, %1};" : "=l"(out) : "r"(__float_as_uint(v)))
#define UNPACK2(lo, hi, in) \
    asm("mov.b64 {%0, %1}, %2;" : "=r"(lo), "=r"(hi) : "l"(in))

__device__ __forceinline__ float ex2(float x) {
    float r; asm("ex2.approx.f32 %0, %1;" : "=f"(r) : "f"(x)); return r;
}
__device__ __forceinline__ float rcp(float x) {
    float r; asm("rcp.approx.f32 %0, %1;" : "=f"(r) : "f"(x)); return r;
}

// Sense-reversing grid barrier (R12 pattern, empirically correct & replay-safe).
// All NBLK blocks are guaranteed resident: 256 blocks, 48KB smem + <=42 regs
// -> 2 blocks/SM -> capacity 296.
__device__ __forceinline__ void grid_barrier(int j) {
    __syncthreads();
    if (threadIdx.x == 0 && threadIdx.y == 0) {
        __threadfence();
        unsigned mygen = g_gen[j];
        unsigned old = atomicAdd(&g_cnt[j], 1u);
        if (old == NBLK - 1) {
            g_cnt[j] = 0;
            __threadfence();
            g_gen[j] = mygen + 1;          // release
        } else {
            while (g_gen[j] == mygen) __nanosleep(64);
        }
        __threadfence();
    }
    __syncthreads();
}

// One pass body. Noise via __ldcg (cross-pass L1 staleness); table via __ldg
// (read-only, never touched pre-barrier -> no stale lines; L1-warm pass 1-3).
template<bool HORIZ, bool LAST>
__device__ __forceinline__ void do_pass(
    const float* __restrict__ nin, float* __restrict__ nout,
    float* __restrict__ disp_out,
    int pix, int pp0, int s0, float sv, float msx, float fw,
    const __half2* __restrict__ brow, int wp1) {

    float np[2][3];
    #pragma unroll
    for (int u = 0; u < 2; u++) {
        const int pp = pp0 + u * 6 * PLANE;
        np[u][1] = __ldcg(nin + pp);
        if (HORIZ) {
            np[u][0] = __ldcg(nin + pp - 1);
            np[u][2] = __ldcg(nin + pp + 1);
        } else {
            np[u][0] = __ldcg(nin + pp - WP);
            np[u][2] = __ldcg(nin + pp + WP);
        }
    }

    float xs[2][3], frac[2][3];
    __half2 dph[2][3];
    #pragma unroll
    for (int u = 0; u < 2; u++) {
        const float wim = fw - fmaf(sv, (float)(s0 + u * 6 + 1), msx);
        #pragma unroll
        for (int c = 0; c < 3; c++) {
            xs[u][c] = fmaf(np[u][c], -sv, wim);
            int k0 = __float2int_rd(xs[u][c]);
            frac[u][c] = xs[u][c] - (float)k0;
            int b0 = wp1 - k0;
            b0 = min(max(b0, 1), BAND - 1);
            dph[u][c] = __ldg(brow + b0 * WW);
        }
    }

    #pragma unroll
    for (int u = 0; u < 2; u++) {
        float e[3];
        #pragma unroll
        for (int c = 0; c < 3; c++) {
            float2 d = __half22float2(dph[u][c]);
            e[c] = ex2(fmaf(d.y - d.x, frac[u][c], d.x));
        }
        const float rZ = rcp(e[0] + e[1] + e[2]);
        const int s = s0 + u * 6;
        if (LAST) {
            float d = e[0] * (fw - xs[u][0]) + e[1] * (fw - xs[u][1])
                    + e[2] * (fw - xs[u][2]);
            disp_out[s * HW + pix] = d * rZ;
        } else {
            nout[pp0 + u * 6 * PLANE] =
                (e[0] * np[u][0] + e[1] * np[u][1] + e[2] * np[u][2]) * rZ;
        }
    }
}

// ---------------------------------------------------------------------------
// Monolithic kernel: phase 0 = prep + half-row band GEMM (per block), then
// 4 propagation passes with grid barriers. grid (2, HH), block (128, 6).
// ---------------------------------------------------------------------------
__global__ __launch_bounds__(768, 2) void pm_mono_kernel(
    const float* __restrict__ left, const float* __restrict__ right,
    const float* __restrict__ minD, const float* __restrict__ maxD,
    const float* __restrict__ noise, float* __restrict__ disp_out) {
    __shared__ float pool[12288];                 // 48 KB
    float (*As)[128] = (float(*)[128])pool;       // 32x128
    float (*Rs)[WW]  = (float(*)[WW])(pool + 4096);
    float (*Sb)[129] = (float(*)[129])pool;       // 74x129, aliases post-GEMM

    const int h = blockIdx.y;
    const int wbase = blockIdx.x * 128;
    const int tid = threadIdx.y * 128 + threadIdx.x;

    // ===== phase 0a: prep (noise copy + mdsv) for this block's w-half =====
    for (int i = tid; i < SS * 128; i += 768) {
        int s = i >> 7, wloc = i & 127;
        g_noiseA[s * PLANE + (h + 1) * WP + wbase + wloc + 1] =
            noise[s * HW + h * WW + wbase + wloc];
    }
    if (tid < 128) {
        int pix = h * WW + wbase + tid;
        float md = fmaxf(__ldg(minD + pix), 0.0f);
        float Md = fmaxf(__ldg(maxD + pix), 0.0f);
        g_mdsv[pix] = make_float2(md, (Md - md) * (1.0f / (float)(SS + 1)));
    }

    // ===== phase 0b: band GEMM for this half-row =====
    for (int i = tid; i < CC * 128; i += 768) {
        int c = i >> 7, wl = i & 127;
        As[c][wl] = left[(c * HH + h) * WW + wbase + wl];
    }
    for (int i = tid; i < CC * WW; i += 768) {
        int c = i >> 8, x = i & 255;
        Rs[c][x] = right[(c * HH + h) * WW + x];
    }
    __syncthreads();

    {
        const int tw = tid / 12;            // 2-wide w-subtile: 0..63
        const int j  = tid % 12;            // band x-tile slot (11 used)
        const int twg8 = (wbase >> 3) + (tw >> 2);
        const int txg = twg8 - 9 + j;
        const bool active = (j < 11) && (txg >= 0) && (txg <= 31);
        const int wl = tw * 2;
        const int x  = txg * 8;

        unsigned long long acc2[2][4];
        #pragma unroll
        for (int i = 0; i < 2; i++)
            #pragma unroll
            for (int q = 0; q < 4; q++) acc2[i][q] = 0ULL;

        if (active) {
            #pragma unroll 8
            for (int k = 0; k < CC; k++) {
                float2 a = *(const float2*)&As[k][wl];
                ulonglong2 t0 = *(const ulonglong2*)&Rs[k][x];
                ulonglong2 t1 = *(const ulonglong2*)&Rs[k][x + 4];
                unsigned long long b2[4] = {t0.x, t0.y, t1.x, t1.y};
                unsigned long long a20, a21;
                PACK2(a20, a.x);
                PACK2(a21, a.y);
                #pragma unroll
                for (int q = 0; q < 4; q++) {
                    FMA2(acc2[0][q], a20, b2[q], acc2[0][q]);
                    FMA2(acc2[1][q], a21, b2[q], acc2[1][q]);
                }
            }
        }
        __syncthreads();   // GEMM smem reads done; pool becomes Sb

        if (active) {
            const int xl = x - wbase;
            #pragma unroll
            for (int i = 0; i < 2; i++) {
                #pragma unroll
                for (int q = 0; q < 8; q++) {
                    unsigned lo, hi;
                    UNPACK2(lo, hi, acc2[i][q >> 1]);
                    float v = __uint_as_float((q & 1) ? hi : lo);
                    int b = wl + i + 1 - xl - q;
                    if (b >= 0 && b <= 73) Sb[b][wl + i] = v;
                }
            }
        }
        __syncthreads();

        const float Cs = 0.21875f * 1.4426950408889634f;   // 7/32*log2(e)
        __half2* dst = g_band2h + h * (BAND * WW) + wbase;
        for (int i2 = tid; i2 < 73 * 128; i2 += 768) {
            int b = (i2 >> 7) + 1;
            int wli = i2 & 127;
            int x0 = wbase + wli + 1 - b;
            float v0 = (x0 >= 0) ? Cs * Sb[b][wli] : 0.0f;
            float v1 = (x0 >= -1 && x0 <= 254) ? Cs * Sb[b - 1][wli] : 0.0f;
            dst[b * WW + wli] = __floats2half2_rn(v0, v1);   // 4B store
        }
    }

    grid_barrier(0);   // table + noiseA + mdsv ready everywhere

    // ===== phases 1-4: propagation passes =====
    const int w = wbase + threadIdx.x;
    const int s0 = threadIdx.y;
    const int pix = h * WW + w;
    const int pp0 = s0 * PLANE + (h + 1) * WP + (w + 1);

    const float2 ms = __ldg(&g_mdsv[pix]);
    const float sv = ms.y;
    const float fw = (float)w;
    const __half2* __restrict__ brow = g_band2h + h * (BAND * WW) + w;
    const int wp1 = w + 1;

    do_pass<true,  false>(g_noiseA, g_noiseB, disp_out, pix, pp0, s0, sv, ms.x, fw, brow, wp1);
    grid_barrier(1);
    do_pass<false, false>(g_noiseB, g_noiseA, disp_out, pix, pp0, s0, sv, ms.x, fw, brow, wp1);
    grid_barrier(2);
    do_pass<true,  false>(g_noiseA, g_noiseB, disp_out, pix, pp0, s0, sv, ms.x, fw, brow, wp1);
    grid_barrier(3);
    do_pass<false, true >(g_noiseB, g_noiseA, disp_out, pix, pp0, s0, sv, ms.x, fw, brow, wp1);
}

extern "C" void kernel_launch(void* const* d_in, const int* in_sizes, int n_in,
                              void* d_out, int out_size) {
    const float* left  = (const float*)d_in[0];
    const float* right = (const float*)d_in[1];
    const float* minD  = (const float*)d_in[2];
    const float* maxD  = (const float*)d_in[3];
    const float* noise = (const float*)d_in[4];
    float* disp = (float*)d_out;

    pm_mono_kernel<<<dim3(2, HH), dim3(128, 6)>>>(left, right, minD, maxD, noise, disp);
}

// round 14
// speedup vs baseline: 1.1593x; 1.1593x over previous
#include <cuda_runtime.h>
#include <cuda_fp16.h>

#define HH 128
#define WW 256
#define SS 12
#define CC 32
#define BAND 74
#define HW (HH * WW)
#define WP 264
#define HP 130
#define PLANE (HP * WP)

// Band pair table, fp16 with baked scale (C = 7/32*log2(e)); 4B access only.
__device__ __half2 g_band2h[HH * BAND * WW];     // 9.7 MB
// Padded noise ping-pong; zero borders (zero-init; only interior written).
__device__ float g_noiseA[SS * PLANE];
__device__ float g_noiseB[SS * PLANE];
__device__ float2 g_mdsv[HW];                    // (max(min,0), search/13)

#define FMA2(d, a, b, c) \
    asm("fma.rn.f32x2 %0, %1, %2, %3;" : "=l"(d) : "l"(a), "l"(b), "l"(c))
#define PACK2(out, v) \
    asm("mov.b64 %0, {%1, %1};" : "=l"(out) : "r"(__float_as_uint(v)))
#define UNPACK2(lo, hi, in) \
    asm("mov.b64 {%0, %1}, %2;" : "=r"(lo), "=r"(hi) : "l"(in))

__device__ __forceinline__ float ex2(float x) {
    float r; asm("ex2.approx.f32 %0, %1;" : "=f"(r) : "f"(x)); return r;
}
__device__ __forceinline__ float rcp(float x) {
    float r; asm("rcp.approx.f32 %0, %1;" : "=f"(r) : "f"(x)); return r;
}

// ---------------------------------------------------------------------------
// Fused front kernel (R11, known good). blockIdx.x 0,1: band GEMM halves.
// blockIdx.x 2: prep. grid (3, HH), 192 threads.
// ---------------------------------------------------------------------------
__global__ __launch_bounds__(192) void front_kernel(
    const float* __restrict__ left, const float* __restrict__ right,
    const float* __restrict__ minD, const float* __restrict__ maxD,
    const float* __restrict__ noise) {
    const int h = blockIdx.y;
    const int tid = threadIdx.x;

    if (blockIdx.x == 2) {
        for (int i = tid; i < SS * WW; i += 192) {
            int s = i >> 8, w = i & 255;
            g_noiseA[s * PLANE + (h + 1) * WP + w + 1] = noise[s * HW + h * WW + w];
        }
        for (int w = tid; w < WW; w += 192) {
            int pix = h * WW + w;
            float md = fmaxf(minD[pix], 0.0f);
            float Md = fmaxf(maxD[pix], 0.0f);
            g_mdsv[pix] = make_float2(md, (Md - md) * (1.0f / (float)(SS + 1)));
        }
        return;
    }

    __shared__ float pool[12288];
    float (*As)[128] = (float(*)[128])pool;
    float (*Rs)[WW]  = (float(*)[WW])(pool + 4096);
    float (*Sb)[129] = (float(*)[129])pool;

    const int wbase = blockIdx.x * 128;

    for (int i = tid; i < CC * 128; i += 192) {
        int c = i >> 7, wl = i & 127;
        As[c][wl] = left[(c * HH + h) * WW + wbase + wl];
    }
    for (int i = tid; i < CC * WW; i += 192) {
        int c = i >> 8, x = i & 255;
        Rs[c][x] = right[(c * HH + h) * WW + x];
    }
    __syncthreads();

    const int tw = tid / 12;
    const int j  = tid % 12;
    const int twg = (wbase >> 3) + tw;
    const int txg = twg - 9 + j;
    const bool active = (j < 11) && (txg >= 0) && (txg <= 31);

    const int wl = tw * 8;
    const int x  = txg * 8;

    unsigned long long acc2[8][4];
    #pragma unroll
    for (int i = 0; i < 8; i++)
        #pragma unroll
        for (int q = 0; q < 4; q++) acc2[i][q] = 0ULL;

    if (active) {
        #pragma unroll 8
        for (int k = 0; k < CC; k++) {
            float a[8];
            *(float4*)&a[0] = *(const float4*)&As[k][wl];
            *(float4*)&a[4] = *(const float4*)&As[k][wl + 4];
            ulonglong2 t0 = *(const ulonglong2*)&Rs[k][x];
            ulonglong2 t1 = *(const ulonglong2*)&Rs[k][x + 4];
            unsigned long long b2[4] = {t0.x, t0.y, t1.x, t1.y};
            #pragma unroll
            for (int i = 0; i < 8; i++) {
                unsigned long long a2;
                PACK2(a2, a[i]);
                #pragma unroll
                for (int q = 0; q < 4; q++)
                    FMA2(acc2[i][q], a2, b2[q], acc2[i][q]);
            }
        }
    }
    __syncthreads();

    if (active) {
        const int xl = x - wbase;
        #pragma unroll
        for (int i = 0; i < 8; i++) {
            #pragma unroll
            for (int q = 0; q < 8; q++) {
                unsigned lo, hi;
                UNPACK2(lo, hi, acc2[i][q >> 1]);
                float v = __uint_as_float((q & 1) ? hi : lo);
                int b = wl + i + 1 - xl - q;
                if (b >= 0 && b <= 73) Sb[b][wl + i] = v;
            }
        }
    }
    __syncthreads();

    const float Cs = 0.21875f * 1.4426950408889634f;   // 7/32 * log2(e)
    __half2* dst = g_band2h + h * BAND * WW + wbase;
    for (int i2 = tid; i2 < 73 * 128; i2 += 192) {
        int b = (i2 >> 7) + 1;
        int wli = i2 & 127;
        int x0 = wbase + wli + 1 - b;
        float v0 = (x0 >= 0) ? Cs * Sb[b][wli] : 0.0f;
        float v1 = (x0 >= -1 && x0 <= 254) ? Cs * Sb[b - 1][wli] : 0.0f;
        dst[b * WW + wli] = __floats2half2_rn(v0, v1);   // 4B store
    }
}

// ---------------------------------------------------------------------------
// One PatchMatch pass: thread = (pixel, samples s0, s0+4, s0+8).
// grid (4, HH) x block (64,4) = 4096 warps; 9 independent gather chains.
// Flow: P0(H) A->B, P1(V) B->A, P2(H) A->B, P3(V) B->disp.
// ---------------------------------------------------------------------------
template<bool HORIZ, bool LAST>
__global__ __launch_bounds__(256) void pm_pass_kernel(float* __restrict__ disp_out) {
    const int w = blockIdx.x * 64 + threadIdx.x;
    const int h = blockIdx.y;
    const int s0 = threadIdx.y;                 // samples s0, s0+4, s0+8
    const int pix = h * WW + w;

    const float* __restrict__ nin  = HORIZ ? g_noiseA : g_noiseB;
    float*       __restrict__ nout = HORIZ ? g_noiseB : g_noiseA;

    const float2 ms = __ldg(&g_mdsv[pix]);
    const float sv = ms.y;
    const float fw = (float)w;

    // --- batch all noise loads up front (9 independent LDG) ---
    const int pp0 = s0 * PLANE + (h + 1) * WP + (w + 1);
    float np[3][3];
    #pragma unroll
    for (int u = 0; u < 3; u++) {
        const int pp = pp0 + u * 4 * PLANE;
        np[u][1] = __ldg(nin + pp);
        if (HORIZ) {
            np[u][0] = __ldg(nin + pp - 1);
            np[u][2] = __ldg(nin + pp + 1);
        } else {
            np[u][0] = __ldg(nin + pp - WP);
            np[u][2] = __ldg(nin + pp + WP);
        }
    }

    const __half2* __restrict__ brow = g_band2h + h * (BAND * WW) + w;
    const int wp1 = w + 1;

    // --- 9 independent 4B gathers ---
    float xs[3][3], frac[3][3];
    __half2 dph[3][3];
    #pragma unroll
    for (int u = 0; u < 3; u++) {
        const float wim = fw - fmaf(sv, (float)(s0 + u * 4 + 1), ms.x);
        #pragma unroll
        for (int c = 0; c < 3; c++) {
            xs[u][c] = fmaf(np[u][c], -sv, wim);
            int k0 = __float2int_rd(xs[u][c]);
            frac[u][c] = xs[u][c] - (float)k0;
            int b0 = wp1 - k0;
            b0 = min(max(b0, 1), BAND - 1);
            dph[u][c] = __ldg(brow + b0 * WW);
        }
    }

    // --- softmax + outputs ---
    #pragma unroll
    for (int u = 0; u < 3; u++) {
        float e[3];
        #pragma unroll
        for (int c = 0; c < 3; c++) {
            float2 d = __half22float2(dph[u][c]);
            e[c] = ex2(fmaf(d.y - d.x, frac[u][c], d.x));
        }
        const float rZ = rcp(e[0] + e[1] + e[2]);
        const int s = s0 + u * 4;
        if (LAST) {
            float d = e[0] * (fw - xs[u][0]) + e[1] * (fw - xs[u][1])
                    + e[2] * (fw - xs[u][2]);
            disp_out[s * HW + pix] = d * rZ;
        } else {
            nout[pp0 + u * 4 * PLANE] =
                (e[0] * np[u][0] + e[1] * np[u][1] + e[2] * np[u][2]) * rZ;
        }
    }
}

extern "C" void kernel_launch(void* const* d_in, const int* in_sizes, int n_in,
                              void* d_out, int out_size) {
    const float* left  = (const float*)d_in[0];
    const float* right = (const float*)d_in[1];
    const float* minD  = (const float*)d_in[2];
    const float* maxD  = (const float*)d_in[3];
    const float* noise = (const float*)d_in[4];
    float* disp = (float*)d_out;

    front_kernel<<<dim3(3, HH), 192>>>(left, right, minD, maxD, noise);

    dim3 grid(4, HH), blk(64, 4);
    pm_pass_kernel<true,  false><<<grid, blk>>>(disp);  // P0 H: A->B
    pm_pass_kernel<false, false><<<grid, blk>>>(disp);  // P1 V: B->A
    pm_pass_kernel<true,  false><<<grid, blk>>>(disp);  // P2 H: A->B
    pm_pass_kernel<false, true ><<<grid, blk>>>(disp);  // P3 V: B->disp
}

// round 15
// speedup vs baseline: 1.3210x; 1.1395x over previous
#include <cuda_runtime.h>
#include <cuda_fp16.h>

#define HH 128
#define WW 256
#define SS 12
#define CC 32
#define BAND 74
#define HW (HH * WW)
#define WP 264
#define HP 130
#define PLANE (HP * WP)

// Band pair table, fp16 with baked scale (C = 7/32*log2(e)); 4B access only.
__device__ __half2 g_band2h[HH * BAND * WW];     // 9.7 MB
// Padded noise ping-pong; zero borders (zero-init; only interior written).
__device__ float g_noiseA[SS * PLANE];
__device__ float g_noiseB[SS * PLANE];
__device__ float2 g_mdsv[HW];                    // (max(min,0), search/13)

#define FMA2(d, a, b, c) \
    asm("fma.rn.f32x2 %0, %1, %2, %3;" : "=l"(d) : "l"(a), "l"(b), "l"(c))
#define PACK2(out, v) \
    asm("mov.b64 %0, {%1, %1};" : "=l"(out) : "r"(__float_as_uint(v)))
#define UNPACK2(lo, hi, in) \
    asm("mov.b64 {%0, %1}, %2;" : "=r"(lo), "=r"(hi) : "l"(in))

__device__ __forceinline__ float ex2(float x) {
    float r; asm("ex2.approx.f32 %0, %1;" : "=f"(r) : "f"(x)); return r;
}
__device__ __forceinline__ float rcp(float x) {
    float r; asm("rcp.approx.f32 %0, %1;" : "=f"(r) : "f"(x)); return r;
}

// ---------------------------------------------------------------------------
// Front kernel: band GEMM + mdsv + FUSED PASS 0 (horizontal, from smem Sb).
// grid (2, HH), 192 threads. Writes: g_band2h, g_mdsv, g_noiseB (padded).
// ---------------------------------------------------------------------------
__global__ __launch_bounds__(192) void front_kernel(
    const float* __restrict__ left, const float* __restrict__ right,
    const float* __restrict__ minD, const float* __restrict__ maxD,
    const float* __restrict__ noise) {
    __shared__ float pool[12288];                 // 48 KB
    float (*As)[128] = (float(*)[128])pool;       // GEMM phase
    float (*Rs)[WW]  = (float(*)[WW])(pool + 4096);
    float (*Sb)[129] = (float(*)[129])pool;       // post-GEMM: 74x129 = 9546
    float2* mdsv_s   = (float2*)(pool + 10240);   // 128 float2, beyond Sb

    const int h = blockIdx.y;
    const int wbase = blockIdx.x * 128;
    const int tid = threadIdx.x;
    const float Cs = 0.21875f * 1.4426950408889634f;   // 7/32 * log2(e)

    for (int i = tid; i < CC * 128; i += 192) {
        int c = i >> 7, wl = i & 127;
        As[c][wl] = left[(c * HH + h) * WW + wbase + wl];
    }
    for (int i = tid; i < CC * WW; i += 192) {
        int c = i >> 8, x = i & 255;
        Rs[c][x] = right[(c * HH + h) * WW + x];
    }
    __syncthreads();

    const int tw = tid / 12;
    const int j  = tid % 12;
    const int twg = (wbase >> 3) + tw;
    const int txg = twg - 9 + j;
    const bool active = (j < 11) && (txg >= 0) && (txg <= 31);

    const int wl = tw * 8;
    const int x  = txg * 8;

    unsigned long long acc2[8][4];
    #pragma unroll
    for (int i = 0; i < 8; i++)
        #pragma unroll
        for (int q = 0; q < 4; q++) acc2[i][q] = 0ULL;

    if (active) {
        #pragma unroll 8
        for (int k = 0; k < CC; k++) {
            float a[8];
            *(float4*)&a[0] = *(const float4*)&As[k][wl];
            *(float4*)&a[4] = *(const float4*)&As[k][wl + 4];
            ulonglong2 t0 = *(const ulonglong2*)&Rs[k][x];
            ulonglong2 t1 = *(const ulonglong2*)&Rs[k][x + 4];
            unsigned long long b2[4] = {t0.x, t0.y, t1.x, t1.y};
            #pragma unroll
            for (int i = 0; i < 8; i++) {
                unsigned long long a2;
                PACK2(a2, a[i]);
                #pragma unroll
                for (int q = 0; q < 4; q++)
                    FMA2(acc2[i][q], a2, b2[q], acc2[i][q]);
            }
        }
    }
    __syncthreads();   // GEMM smem reads done; pool becomes Sb + mdsv_s

    // Stage accumulators into band layout + mdsv (Rs region is dead now).
    if (active) {
        const int xl = x - wbase;
        #pragma unroll
        for (int i = 0; i < 8; i++) {
            #pragma unroll
            for (int q = 0; q < 8; q++) {
                unsigned lo, hi;
                UNPACK2(lo, hi, acc2[i][q >> 1]);
                float v = __uint_as_float((q & 1) ? hi : lo);
                int b = wl + i + 1 - xl - q;
                if (b >= 0 && b <= 73) Sb[b][wl + i] = v;
            }
        }
    }
    if (tid < 128) {
        int pix = h * WW + wbase + tid;
        float md = fmaxf(__ldg(minD + pix), 0.0f);
        float Md = fmaxf(__ldg(maxD + pix), 0.0f);
        float2 v = make_float2(md, (Md - md) * (1.0f / (float)(SS + 1)));
        mdsv_s[tid] = v;
        g_mdsv[pix] = v;
    }
    __syncthreads();

    // Table writeout (fp16 pairs, zero-fill out-of-image x).
    __half2* dst = g_band2h + h * BAND * WW + wbase;
    for (int i2 = tid; i2 < 73 * 128; i2 += 192) {
        int b = (i2 >> 7) + 1;
        int wli = i2 & 127;
        int x0 = wbase + wli + 1 - b;
        float v0 = (x0 >= 0) ? Cs * Sb[b][wli] : 0.0f;
        float v1 = (x0 >= -1 && x0 <= 254) ? Cs * Sb[b - 1][wli] : 0.0f;
        dst[b * WW + wli] = __floats2half2_rn(v0, v1);
    }

    // ===== FUSED PASS 0 (horizontal): ext noise -> padded g_noiseB =====
    for (int i = tid; i < 128 * SS; i += 192) {
        const int wli = i & 127;
        const int s   = i >> 7;
        const int w   = wbase + wli;
        const float2 ms = mdsv_s[wli];
        const float sv = ms.y;
        const float fw = (float)w;

        const int nb = s * HW + h * WW + w;
        float np[3];
        np[1] = __ldg(noise + nb);
        np[0] = (w > 0)      ? __ldg(noise + nb - 1) : 0.0f;
        np[2] = (w < WW - 1) ? __ldg(noise + nb + 1) : 0.0f;

        const float wim = fw - fmaf(sv, (float)(s + 1), ms.x);
        float e[3];
        #pragma unroll
        for (int c = 0; c < 3; c++) {
            float xs = fmaf(np[c], -sv, wim);
            int k0 = __float2int_rd(xs);
            float frac = xs - (float)k0;
            int b0 = w + 1 - k0;
            b0 = min(max(b0, 1), BAND - 1);
            int x0 = w + 1 - b0;
            float d0 = (x0 >= 0)  ? Sb[b0][wli]     : 0.0f;
            float d1 = (x0 <= 254)? Sb[b0 - 1][wli] : 0.0f;
            e[c] = ex2(fmaf(d1 - d0, frac, d0) * Cs);
        }
        const float rZ = rcp(e[0] + e[1] + e[2]);
        g_noiseB[s * PLANE + (h + 1) * WP + w + 1] =
            (e[0] * np[0] + e[1] * np[1] + e[2] * np[2]) * rZ;
    }
}

// ---------------------------------------------------------------------------
// Propagation pass (R11 shape): thread = (pixel, samples s0 and s0+6).
// grid (4, HH) x block (64,6). P1(V) B->A, P2(H) A->B, P3(V) B->disp.
// ---------------------------------------------------------------------------
template<bool HORIZ, bool LAST>
__global__ __launch_bounds__(384) void pm_pass_kernel(float* __restrict__ disp_out) {
    const int w = blockIdx.x * 64 + threadIdx.x;
    const int h = blockIdx.y;
    const int s0 = threadIdx.y;                 // samples s0, s0+6
    const int pix = h * WW + w;

    const float* __restrict__ nin  = HORIZ ? g_noiseA : g_noiseB;
    float*       __restrict__ nout = HORIZ ? g_noiseB : g_noiseA;

    const float2 ms = __ldg(&g_mdsv[pix]);
    const float sv = ms.y;
    const float fw = (float)w;

    const int pp0 = s0 * PLANE + (h + 1) * WP + (w + 1);
    float np[2][3];
    #pragma unroll
    for (int u = 0; u < 2; u++) {
        const int pp = pp0 + u * 6 * PLANE;
        np[u][1] = __ldg(nin + pp);
        if (HORIZ) {
            np[u][0] = __ldg(nin + pp - 1);
            np[u][2] = __ldg(nin + pp + 1);
        } else {
            np[u][0] = __ldg(nin + pp - WP);
            np[u][2] = __ldg(nin + pp + WP);
        }
    }

    const __half2* __restrict__ brow = g_band2h + h * (BAND * WW) + w;
    const int wp1 = w + 1;

    float xs[2][3], frac[2][3];
    __half2 dph[2][3];
    #pragma unroll
    for (int u = 0; u < 2; u++) {
        const float wim = fw - fmaf(sv, (float)(s0 + u * 6 + 1), ms.x);
        #pragma unroll
        for (int c = 0; c < 3; c++) {
            xs[u][c] = fmaf(np[u][c], -sv, wim);
            int k0 = __float2int_rd(xs[u][c]);
            frac[u][c] = xs[u][c] - (float)k0;
            int b0 = wp1 - k0;
            b0 = min(max(b0, 1), BAND - 1);
            dph[u][c] = __ldg(brow + b0 * WW);
        }
    }

    #pragma unroll
    for (int u = 0; u < 2; u++) {
        float e[3];
        #pragma unroll
        for (int c = 0; c < 3; c++) {
            float2 d = __half22float2(dph[u][c]);
            e[c] = ex2(fmaf(d.y - d.x, frac[u][c], d.x));
        }
        const float rZ = rcp(e[0] + e[1] + e[2]);
        const int s = s0 + u * 6;
        if (LAST) {
            float d = e[0] * (fw - xs[u][0]) + e[1] * (fw - xs[u][1])
                    + e[2] * (fw - xs[u][2]);
            disp_out[s * HW + pix] = d * rZ;
        } else {
            nout[pp0 + u * 6 * PLANE] =
                (e[0] * np[u][0] + e[1] * np[u][1] + e[2] * np[u][2]) * rZ;
        }
    }
}

extern "C" void kernel_launch(void* const* d_in, const int* in_sizes, int n_in,
                              void* d_out, int out_size) {
    const float* left  = (const float*)d_in[0];
    const float* right = (const float*)d_in[1];
    const float* minD  = (const float*)d_in[2];
    const float* maxD  = (const float*)d_in[3];
    const float* noise = (const float*)d_in[4];
    float* disp = (float*)d_out;

    // Front: GEMM + mdsv + fused pass 0 (H, ext noise -> g_noiseB).
    front_kernel<<<dim3(2, HH), 192>>>(left, right, minD, maxD, noise);

    dim3 grid(4, HH), blk(64, 6);
    pm_pass_kernel<false, false><<<grid, blk>>>(disp);  // P1 V: B->A
    pm_pass_kernel<true,  false><<<grid, blk>>>(disp);  // P2 H: A->B
    pm_pass_kernel<false, true ><<<grid, blk>>>(disp);  // P3 V: B->disp
}

// round 16
// speedup vs baseline: 1.4015x; 1.0609x over previous
#include <cuda_runtime.h>
#include <cuda_fp16.h>

#define HH 128
#define WW 256
#define SS 12
#define CC 32
#define BAND 74
#define HW (HH * WW)
#define WP 264
#define HP 130
#define PLANE (HP * WP)

// Band pair table, fp16 with baked scale (C = 7/32*log2(e)); 4B access only.
__device__ __half2 g_band2h[HH * BAND * WW];     // 9.7 MB
// Padded noise ping-pong; zero borders (zero-init; only interior written).
__device__ float g_noiseA[SS * PLANE];
__device__ float g_noiseB[SS * PLANE];
__device__ float2 g_mdsv[HW];                    // (max(min,0), search/13)

#define FMA2(d, a, b, c) \
    asm("fma.rn.f32x2 %0, %1, %2, %3;" : "=l"(d) : "l"(a), "l"(b), "l"(c))
#define PACK2(out, v) \
    asm("mov.b64 %0, {%1, %1};" : "=l"(out) : "r"(__float_as_uint(v)))
#define UNPACK2(lo, hi, in) \
    asm("mov.b64 {%0, %1}, %2;" : "=r"(lo), "=r"(hi) : "l"(in))

__device__ __forceinline__ float ex2(float x) {
    float r; asm("ex2.approx.f32 %0, %1;" : "=f"(r) : "f"(x)); return r;
}
__device__ __forceinline__ float rcp(float x) {
    float r; asm("rcp.approx.f32 %0, %1;" : "=f"(r) : "f"(x)); return r;
}

// ---------------------------------------------------------------------------
// Front kernel: band GEMM + mdsv + FUSED PASS 0 (horizontal, from smem Sb).
// grid (2, HH), 192 threads. Writes: g_band2h, g_mdsv, g_noiseB (padded).
// ---------------------------------------------------------------------------
__global__ __launch_bounds__(192) void front_kernel(
    const float* __restrict__ left, const float* __restrict__ right,
    const float* __restrict__ minD, const float* __restrict__ maxD,
    const float* __restrict__ noise) {
    __shared__ float pool[12288];                 // 48 KB
    float (*As)[128] = (float(*)[128])pool;       // GEMM phase
    float (*Rs)[WW]  = (float(*)[WW])(pool + 4096);
    float (*Sb)[129] = (float(*)[129])pool;       // post-GEMM: 74x129 = 9546
    float2* mdsv_s   = (float2*)(pool + 10240);   // 128 float2, beyond Sb

    const int h = blockIdx.y;
    const int wbase = blockIdx.x * 128;
    const int tid = threadIdx.x;
    const float Cs = 0.21875f * 1.4426950408889634f;   // 7/32 * log2(e)

    for (int i = tid; i < CC * 128; i += 192) {
        int c = i >> 7, wl = i & 127;
        As[c][wl] = left[(c * HH + h) * WW + wbase + wl];
    }
    for (int i = tid; i < CC * WW; i += 192) {
        int c = i >> 8, x = i & 255;
        Rs[c][x] = right[(c * HH + h) * WW + x];
    }
    __syncthreads();

    const int tw = tid / 12;
    const int j  = tid % 12;
    const int twg = (wbase >> 3) + tw;
    const int txg = twg - 9 + j;
    const bool active = (j < 11) && (txg >= 0) && (txg <= 31);

    const int wl = tw * 8;
    const int x  = txg * 8;

    unsigned long long acc2[8][4];
    #pragma unroll
    for (int i = 0; i < 8; i++)
        #pragma unroll
        for (int q = 0; q < 4; q++) acc2[i][q] = 0ULL;

    if (active) {
        #pragma unroll 8
        for (int k = 0; k < CC; k++) {
            float a[8];
            *(float4*)&a[0] = *(const float4*)&As[k][wl];
            *(float4*)&a[4] = *(const float4*)&As[k][wl + 4];
            ulonglong2 t0 = *(const ulonglong2*)&Rs[k][x];
            ulonglong2 t1 = *(const ulonglong2*)&Rs[k][x + 4];
            unsigned long long b2[4] = {t0.x, t0.y, t1.x, t1.y};
            #pragma unroll
            for (int i = 0; i < 8; i++) {
                unsigned long long a2;
                PACK2(a2, a[i]);
                #pragma unroll
                for (int q = 0; q < 4; q++)
                    FMA2(acc2[i][q], a2, b2[q], acc2[i][q]);
            }
        }
    }
    __syncthreads();   // GEMM smem reads done; pool becomes Sb + mdsv_s

    if (active) {
        const int xl = x - wbase;
        #pragma unroll
        for (int i = 0; i < 8; i++) {
            #pragma unroll
            for (int q = 0; q < 8; q++) {
                unsigned lo, hi;
                UNPACK2(lo, hi, acc2[i][q >> 1]);
                float v = __uint_as_float((q & 1) ? hi : lo);
                int b = wl + i + 1 - xl - q;
                if (b >= 0 && b <= 73) Sb[b][wl + i] = v;
            }
        }
    }
    if (tid < 128) {
        int pix = h * WW + wbase + tid;
        float md = fmaxf(__ldg(minD + pix), 0.0f);
        float Md = fmaxf(__ldg(maxD + pix), 0.0f);
        float2 v = make_float2(md, (Md - md) * (1.0f / (float)(SS + 1)));
        mdsv_s[tid] = v;
        g_mdsv[pix] = v;
    }
    __syncthreads();

    // Table writeout (fp16 pairs, zero-fill out-of-image x).
    __half2* dst = g_band2h + h * BAND * WW + wbase;
    for (int i2 = tid; i2 < 73 * 128; i2 += 192) {
        int b = (i2 >> 7) + 1;
        int wli = i2 & 127;
        int x0 = wbase + wli + 1 - b;
        float v0 = (x0 >= 0) ? Cs * Sb[b][wli] : 0.0f;
        float v1 = (x0 >= -1 && x0 <= 254) ? Cs * Sb[b - 1][wli] : 0.0f;
        dst[b * WW + wli] = __floats2half2_rn(v0, v1);
    }

    // ===== FUSED PASS 0 (horizontal): ext noise -> padded g_noiseB =====
    for (int i = tid; i < 128 * SS; i += 192) {
        const int wli = i & 127;
        const int s   = i >> 7;
        const int w   = wbase + wli;
        const float2 ms = mdsv_s[wli];
        const float sv = ms.y;
        const float fw = (float)w;

        const int nb = s * HW + h * WW + w;
        float np[3];
        np[1] = __ldg(noise + nb);
        np[0] = (w > 0)      ? __ldg(noise + nb - 1) : 0.0f;
        np[2] = (w < WW - 1) ? __ldg(noise + nb + 1) : 0.0f;

        const float wim = fw - fmaf(sv, (float)(s + 1), ms.x);
        float e[3];
        #pragma unroll
        for (int c = 0; c < 3; c++) {
            float xs = fmaf(np[c], -sv, wim);
            int k0 = __float2int_rd(xs);
            float frac = xs - (float)k0;
            int b0 = w + 1 - k0;
            b0 = min(max(b0, 1), BAND - 1);
            int x0 = w + 1 - b0;
            float d0 = (x0 >= 0)              ? Sb[b0][wli]     : 0.0f;
            float d1 = (x0 >= -1 && x0 <= 254)? Sb[b0 - 1][wli] : 0.0f;
            e[c] = ex2(fmaf(d1 - d0, frac, d0) * Cs);
        }
        const float rZ = rcp(e[0] + e[1] + e[2]);
        g_noiseB[s * PLANE + (h + 1) * WP + w + 1] =
            (e[0] * np[0] + e[1] * np[1] + e[2] * np[2]) * rZ;
    }

#if __CUDA_ARCH__ >= 900
    cudaTriggerProgrammaticLaunchCompletion();
#endif
}

// ---------------------------------------------------------------------------
// Propagation pass (R11 shape): thread = (pixel, samples s0 and s0+6).
// grid (4, HH) x block (64,6). P1(V) B->A, P2(H) A->B, P3(V) B->disp.
// PDL: sync on predecessor before first dependent load; trigger at end.
// ---------------------------------------------------------------------------
template<bool HORIZ, bool LAST>
__global__ __launch_bounds__(384) void pm_pass_kernel(float* __restrict__ disp_out) {
    const int w = blockIdx.x * 64 + threadIdx.x;
    const int h = blockIdx.y;
    const int s0 = threadIdx.y;                 // samples s0, s0+6
    const int pix = h * WW + w;
    const int pp0 = s0 * PLANE + (h + 1) * WP + (w + 1);
    const int wp1 = w + 1;
    const float fw = (float)w;
    const __half2* __restrict__ brow = g_band2h + h * (BAND * WW) + w;

    const float* __restrict__ nin  = HORIZ ? g_noiseA : g_noiseB;
    float*       __restrict__ nout = HORIZ ? g_noiseB : g_noiseA;

#if __CUDA_ARCH__ >= 900
    cudaGridDependencySynchronize();           // wait for predecessor writes
#endif

    const float2 ms = __ldg(&g_mdsv[pix]);
    const float sv = ms.y;

    float np[2][3];
    #pragma unroll
    for (int u = 0; u < 2; u++) {
        const int pp = pp0 + u * 6 * PLANE;
        np[u][1] = __ldg(nin + pp);
        if (HORIZ) {
            np[u][0] = __ldg(nin + pp - 1);
            np[u][2] = __ldg(nin + pp + 1);
        } else {
            np[u][0] = __ldg(nin + pp - WP);
            np[u][2] = __ldg(nin + pp + WP);
        }
    }

    float xs[2][3], frac[2][3];
    __half2 dph[2][3];
    #pragma unroll
    for (int u = 0; u < 2; u++) {
        const float wim = fw - fmaf(sv, (float)(s0 + u * 6 + 1), ms.x);
        #pragma unroll
        for (int c = 0; c < 3; c++) {
            xs[u][c] = fmaf(np[u][c], -sv, wim);
            int k0 = __float2int_rd(xs[u][c]);
            frac[u][c] = xs[u][c] - (float)k0;
            int b0 = wp1 - k0;
            b0 = min(max(b0, 1), BAND - 1);
            dph[u][c] = __ldg(brow + b0 * WW);
        }
    }

    #pragma unroll
    for (int u = 0; u < 2; u++) {
        float e[3];
        #pragma unroll
        for (int c = 0; c < 3; c++) {
            float2 d = __half22float2(dph[u][c]);
            e[c] = ex2(fmaf(d.y - d.x, frac[u][c], d.x));
        }
        const float rZ = rcp(e[0] + e[1] + e[2]);
        const int s = s0 + u * 6;
        if (LAST) {
            float d = e[0] * (fw - xs[u][0]) + e[1] * (fw - xs[u][1])
                    + e[2] * (fw - xs[u][2]);
            disp_out[s * HW + pix] = d * rZ;
        } else {
            nout[pp0 + u * 6 * PLANE] =
                (e[0] * np[u][0] + e[1] * np[u][1] + e[2] * np[u][2]) * rZ;
        }
    }

#if __CUDA_ARCH__ >= 900
    if (!LAST) cudaTriggerProgrammaticLaunchCompletion();
#endif
}

// Host-side PDL launch helper for the pass kernels.
template<bool HORIZ, bool LAST>
static void launch_pass_pdl(float* disp) {
    cudaLaunchConfig_t cfg = {};
    cfg.gridDim = dim3(4, HH, 1);
    cfg.blockDim = dim3(64, 6, 1);
    cfg.dynamicSmemBytes = 0;
    cfg.stream = 0;
    cudaLaunchAttribute at[1];
    at[0].id = cudaLaunchAttributeProgrammaticStreamSerialization;
    at[0].val.programmaticStreamSerializationAllowed = 1;
    cfg.attrs = at;
    cfg.numAttrs = 1;
    cudaLaunchKernelEx(&cfg, pm_pass_kernel<HORIZ, LAST>, disp);
}

extern "C" void kernel_launch(void* const* d_in, const int* in_sizes, int n_in,
                              void* d_out, int out_size) {
    const float* left  = (const float*)d_in[0];
    const float* right = (const float*)d_in[1];
    const float* minD  = (const float*)d_in[2];
    const float* maxD  = (const float*)d_in[3];
    const float* noise = (const float*)d_in[4];
    float* disp = (float*)d_out;

    // Front: GEMM + mdsv + fused pass 0 (H, ext noise -> g_noiseB).
    front_kernel<<<dim3(2, HH), 192>>>(left, right, minD, maxD, noise);

    launch_pass_pdl<false, false>(disp);   // P1 V: B->A
    launch_pass_pdl<true,  false>(disp);   // P2 H: A->B
    launch_pass_pdl<false, true >(disp);   // P3 V: B->disp
}

// round 17
// speedup vs baseline: 1.5064x; 1.0749x over previous
#include <cuda_runtime.h>
#include <cuda_fp16.h>

#define HH 128
#define WW 256
#define SS 12
#define CC 32
#define BAND 74
#define HW (HH * WW)
#define WP 264
#define HP 130
#define PLANE (HP * WP)

// Band pair table, fp16 with baked scale (C = 7/32*log2(e)); 4B access only.
__device__ __half2 g_band2h[HH * BAND * WW];     // 9.7 MB
// Padded noise ping-pong, PACKED sample pairs: element [p][y][x] is
// half2(noise[s=p], noise[s=p+6]) at pixel (y-1, x-1). p in [0,6).
// Zero borders (zero-init; only interior written).
__device__ __half2 g_noiseA[6 * PLANE];
__device__ __half2 g_noiseB[6 * PLANE];
__device__ float2 g_mdsv[HW];                    // (max(min,0), search/13)

#define FMA2(d, a, b, c) \
    asm("fma.rn.f32x2 %0, %1, %2, %3;" : "=l"(d) : "l"(a), "l"(b), "l"(c))
#define PACK2(out, v) \
    asm("mov.b64 %0, {%1, %1};" : "=l"(out) : "r"(__float_as_uint(v)))
#define UNPACK2(lo, hi, in) \
    asm("mov.b64 {%0, %1}, %2;" : "=r"(lo), "=r"(hi) : "l"(in))

__device__ __forceinline__ float ex2(float x) {
    float r; asm("ex2.approx.f32 %0, %1;" : "=f"(r) : "f"(x)); return r;
}
__device__ __forceinline__ float rcp(float x) {
    float r; asm("rcp.approx.f32 %0, %1;" : "=f"(r) : "f"(x)); return r;
}

// ---------------------------------------------------------------------------
// Front kernel: band GEMM + mdsv + FUSED PASS 0 (horizontal, from smem Sb),
// emitting packed half2 sample-pair noise. grid (2, HH), 192 threads.
// ---------------------------------------------------------------------------
__global__ __launch_bounds__(192) void front_kernel(
    const float* __restrict__ left, const float* __restrict__ right,
    const float* __restrict__ minD, const float* __restrict__ maxD,
    const float* __restrict__ noise) {
    __shared__ float pool[12288];                 // 48 KB
    float (*As)[128] = (float(*)[128])pool;       // GEMM phase
    float (*Rs)[WW]  = (float(*)[WW])(pool + 4096);
    float (*Sb)[129] = (float(*)[129])pool;       // post-GEMM: 74x129 = 9546
    float2* mdsv_s   = (float2*)(pool + 10240);   // 128 float2, beyond Sb

    const int h = blockIdx.y;
    const int wbase = blockIdx.x * 128;
    const int tid = threadIdx.x;
    const float Cs = 0.21875f * 1.4426950408889634f;   // 7/32 * log2(e)

    for (int i = tid; i < CC * 128; i += 192) {
        int c = i >> 7, wl = i & 127;
        As[c][wl] = left[(c * HH + h) * WW + wbase + wl];
    }
    for (int i = tid; i < CC * WW; i += 192) {
        int c = i >> 8, x = i & 255;
        Rs[c][x] = right[(c * HH + h) * WW + x];
    }
    __syncthreads();

    const int tw = tid / 12;
    const int j  = tid % 12;
    const int twg = (wbase >> 3) + tw;
    const int txg = twg - 9 + j;
    const bool active = (j < 11) && (txg >= 0) && (txg <= 31);

    const int wl = tw * 8;
    const int x  = txg * 8;

    unsigned long long acc2[8][4];
    #pragma unroll
    for (int i = 0; i < 8; i++)
        #pragma unroll
        for (int q = 0; q < 4; q++) acc2[i][q] = 0ULL;

    if (active) {
        #pragma unroll 8
        for (int k = 0; k < CC; k++) {
            float a[8];
            *(float4*)&a[0] = *(const float4*)&As[k][wl];
            *(float4*)&a[4] = *(const float4*)&As[k][wl + 4];
            ulonglong2 t0 = *(const ulonglong2*)&Rs[k][x];
            ulonglong2 t1 = *(const ulonglong2*)&Rs[k][x + 4];
            unsigned long long b2[4] = {t0.x, t0.y, t1.x, t1.y};
            #pragma unroll
            for (int i = 0; i < 8; i++) {
                unsigned long long a2;
                PACK2(a2, a[i]);
                #pragma unroll
                for (int q = 0; q < 4; q++)
                    FMA2(acc2[i][q], a2, b2[q], acc2[i][q]);
            }
        }
    }
    __syncthreads();   // GEMM smem reads done; pool becomes Sb + mdsv_s

    if (active) {
        const int xl = x - wbase;
        #pragma unroll
        for (int i = 0; i < 8; i++) {
            #pragma unroll
            for (int q = 0; q < 8; q++) {
                unsigned lo, hi;
                UNPACK2(lo, hi, acc2[i][q >> 1]);
                float v = __uint_as_float((q & 1) ? hi : lo);
                int b = wl + i + 1 - xl - q;
                if (b >= 0 && b <= 73) Sb[b][wl + i] = v;
            }
        }
    }
    if (tid < 128) {
        int pix = h * WW + wbase + tid;
        float md = fmaxf(__ldg(minD + pix), 0.0f);
        float Md = fmaxf(__ldg(maxD + pix), 0.0f);
        float2 v = make_float2(md, (Md - md) * (1.0f / (float)(SS + 1)));
        mdsv_s[tid] = v;
        g_mdsv[pix] = v;
    }
    __syncthreads();

    // Table writeout (fp16 pairs, zero-fill out-of-image x).
    __half2* dst = g_band2h + h * BAND * WW + wbase;
    for (int i2 = tid; i2 < 73 * 128; i2 += 192) {
        int b = (i2 >> 7) + 1;
        int wli = i2 & 127;
        int x0 = wbase + wli + 1 - b;
        float v0 = (x0 >= 0) ? Cs * Sb[b][wli] : 0.0f;
        float v1 = (x0 >= -1 && x0 <= 254) ? Cs * Sb[b - 1][wli] : 0.0f;
        dst[b * WW + wli] = __floats2half2_rn(v0, v1);
    }

    // ===== FUSED PASS 0 (H): ext fp32 noise -> packed half2 g_noiseB =====
    for (int i = tid; i < 128 * 6; i += 192) {
        const int wli = i & 127;
        const int p   = i >> 7;                  // pair id: samples p, p+6
        const int w   = wbase + wli;
        const float2 ms = mdsv_s[wli];
        const float sv = ms.y;
        const float fw = (float)w;

        float res[2];
        #pragma unroll
        for (int u = 0; u < 2; u++) {
            const int s = p + u * 6;
            const int nb = s * HW + h * WW + w;
            float np[3];
            np[1] = __ldg(noise + nb);
            np[0] = (w > 0)      ? __ldg(noise + nb - 1) : 0.0f;
            np[2] = (w < WW - 1) ? __ldg(noise + nb + 1) : 0.0f;

            const float wim = fw - fmaf(sv, (float)(s + 1), ms.x);
            float e[3];
            #pragma unroll
            for (int c = 0; c < 3; c++) {
                float xs = fmaf(np[c], -sv, wim);
                int k0 = __float2int_rd(xs);
                float frac = xs - (float)k0;
                int b0 = w + 1 - k0;
                b0 = min(max(b0, 1), BAND - 1);
                int x0 = w + 1 - b0;
                float d0 = (x0 >= 0)               ? Sb[b0][wli]     : 0.0f;
                float d1 = (x0 >= -1 && x0 <= 254) ? Sb[b0 - 1][wli] : 0.0f;
                e[c] = ex2(fmaf(d1 - d0, frac, d0) * Cs);
            }
            const float rZ = rcp(e[0] + e[1] + e[2]);
            res[u] = (e[0] * np[0] + e[1] * np[1] + e[2] * np[2]) * rZ;
        }
        g_noiseB[p * PLANE + (h + 1) * WP + w + 1] =
            __floats2half2_rn(res[0], res[1]);
    }

#if __CUDA_ARCH__ >= 900
    cudaTriggerProgrammaticLaunchCompletion();
#endif
}

// ---------------------------------------------------------------------------
// Propagation pass: thread = (pixel, sample pair p = {s, s+6}); packed half2
// noise halves load/store count. grid (4, HH) x block (64,6).
// P1(V) B->A, P2(H) A->B, P3(V) B->disp. PDL chained.
// ---------------------------------------------------------------------------
template<bool HORIZ, bool LAST>
__global__ __launch_bounds__(384) void pm_pass_kernel(float* __restrict__ disp_out) {
    const int w = blockIdx.x * 64 + threadIdx.x;
    const int h = blockIdx.y;
    const int p = threadIdx.y;                  // pair: samples p, p+6
    const int pix = h * WW + w;
    const int pp = p * PLANE + (h + 1) * WP + (w + 1);
    const int wp1 = w + 1;
    const float fw = (float)w;
    const __half2* __restrict__ brow = g_band2h + h * (BAND * WW) + w;

    const __half2* __restrict__ nin  = HORIZ ? g_noiseA : g_noiseB;
    __half2*       __restrict__ nout = HORIZ ? g_noiseB : g_noiseA;

#if __CUDA_ARCH__ >= 900
    cudaGridDependencySynchronize();           // wait for predecessor writes
#endif

    const float2 ms = __ldg(&g_mdsv[pix]);
    const float sv = ms.y;

    // --- 3 packed noise taps: each yields both samples' value ---
    float2 np[3];                               // np[c] = (sample p, sample p+6)
    np[1] = __half22float2(nin[pp]);
    if (HORIZ) {
        np[0] = __half22float2(nin[pp - 1]);
        np[2] = __half22float2(nin[pp + 1]);
    } else {
        np[0] = __half22float2(nin[pp - WP]);
        np[2] = __half22float2(nin[pp + WP]);
    }

    // --- 6 independent gathers ---
    float xs[2][3], frac[2][3];
    __half2 dph[2][3];
    #pragma unroll
    for (int u = 0; u < 2; u++) {
        const float wim = fw - fmaf(sv, (float)(p + u * 6 + 1), ms.x);
        #pragma unroll
        for (int c = 0; c < 3; c++) {
            float npv = (u == 0) ? np[c].x : np[c].y;
            xs[u][c] = fmaf(npv, -sv, wim);
            int k0 = __float2int_rd(xs[u][c]);
            frac[u][c] = xs[u][c] - (float)k0;
            int b0 = wp1 - k0;
            b0 = min(max(b0, 1), BAND - 1);
            dph[u][c] = __ldg(brow + b0 * WW);
        }
    }

    // --- softmax + outputs ---
    float res[2];
    #pragma unroll
    for (int u = 0; u < 2; u++) {
        float e[3];
        #pragma unroll
        for (int c = 0; c < 3; c++) {
            float2 d = __half22float2(dph[u][c]);
            e[c] = ex2(fmaf(d.y - d.x, frac[u][c], d.x));
        }
        const float rZ = rcp(e[0] + e[1] + e[2]);
        if (LAST) {
            float d = e[0] * (fw - xs[u][0]) + e[1] * (fw - xs[u][1])
                    + e[2] * (fw - xs[u][2]);
            disp_out[(p + u * 6) * HW + pix] = d * rZ;
        } else {
            float n0 = (u == 0) ? np[0].x : np[0].y;
            float n1 = (u == 0) ? np[1].x : np[1].y;
            float n2 = (u == 0) ? np[2].x : np[2].y;
            res[u] = (e[0] * n0 + e[1] * n1 + e[2] * n2) * rZ;
        }
    }
    if (!LAST) nout[pp] = __floats2half2_rn(res[0], res[1]);

#if __CUDA_ARCH__ >= 900
    if (!LAST) cudaTriggerProgrammaticLaunchCompletion();
#endif
}

// Host-side PDL launch helper for the pass kernels.
template<bool HORIZ, bool LAST>
static void launch_pass_pdl(float* disp) {
    cudaLaunchConfig_t cfg = {};
    cfg.gridDim = dim3(4, HH, 1);
    cfg.blockDim = dim3(64, 6, 1);
    cfg.dynamicSmemBytes = 0;
    cfg.stream = 0;
    cudaLaunchAttribute at[1];
    at[0].id = cudaLaunchAttributeProgrammaticStreamSerialization;
    at[0].val.programmaticStreamSerializationAllowed = 1;
    cfg.attrs = at;
    cfg.numAttrs = 1;
    cudaLaunchKernelEx(&cfg, pm_pass_kernel<HORIZ, LAST>, disp);
}

extern "C" void kernel_launch(void* const* d_in, const int* in_sizes, int n_in,
                              void* d_out, int out_size) {
    const float* left  = (const float*)d_in[0];
    const float* right = (const float*)d_in[1];
    const float* minD  = (const float*)d_in[2];
    const float* maxD  = (const float*)d_in[3];
    const float* noise = (const float*)d_in[4];
    float* disp = (float*)d_out;

    // Front: GEMM + mdsv + fused pass 0 (H, ext noise -> packed g_noiseB).
    front_kernel<<<dim3(2, HH), 192>>>(left, right, minD, maxD, noise);

    launch_pass_pdl<false, false>(disp);   // P1 V: B->A
    launch_pass_pdl<true,  false>(disp);   // P2 H: A->B
    launch_pass_pdl<false, true >(disp);   // P3 V: B->disp
}